// round 16
// baseline (speedup 1.0000x reference)
#include <cuda_runtime.h>
#include <cuda_fp16.h>
#include <cuda_bf16.h>

// Problem constants
#define Bn 4
#define Cn 64
#define Hn 96
#define Wn 96
#define PLANE (Hn*Wn)            // 9216
#define NPLANES (Bn*Cn)          // 256
#define NTOT (NPLANES*PLANE)     // 2359296
#define CNT_PER_CH (Bn*PLANE)    // 36864
#define BN_EPS 1e-5f
#define NPART 36                 // partial sums per channel
#define GRIDF 576                // fused grid (4 blocks/SM x 148 = 592 slots)
#define TPB 4                    // tiles per block: 2304 / 576

// Scratch (__device__ globals; allocation-free rule)
__device__ float    g_psum[Cn * NPART];
__device__ float    g_psq [Cn * NPART];
__device__ unsigned g_count = 0;   // grid barrier arrival counter
__device__ unsigned g_sense = 0;   // grid barrier sense (flips each launch)

__device__ __forceinline__ float silu_f(float x) {
    return __fdividef(x, 1.0f + __expf(-x));
}

// Prefetch one tile's 34x34 halo into registers (5 elements per thread).
__device__ __forceinline__ void prefetch_tile(const float* __restrict__ x,
                                              int t, int tid, float* pre) {
    const int plane = t / 9, tq = t % 9;
    const int ty0 = (tq / 3) * 32, tx0 = (tq % 3) * 32;
    const float* xp = x + plane * PLANE;
    #pragma unroll
    for (int j = 0; j < 5; j++) {
        const int i = tid + j * 256;
        float v = 0.0f;
        if (i < 1156) {
            int hy = i / 34, hx = i % 34;
            int gy = ty0 + hy - 1, gx = tx0 + hx - 1;
            if (gy >= 0 && gy < Hn && gx >= 0 && gx < Wn) v = xp[gy * Wn + gx];
        }
        pre[j] = v;
    }
}

// ---------------------------------------------------------------------------
// Single fused kernel: 4 conv tiles per block (prefetch-pipelined), y kept in
// smem across a grid barrier, per-warp stats, BN+ReLU applied from smem.
// ---------------------------------------------------------------------------
__global__ __launch_bounds__(256, 4)
void kan_fused_kernel(const float* __restrict__ x,
                      const float* __restrict__ base_weight,    // (9)
                      const float* __restrict__ spline_weight,  // (9,8)
                      const float* __restrict__ spline_scaler,  // (9)
                      const float* __restrict__ gamma,
                      const float* __restrict__ beta,
                      float* __restrict__ out)
{
    __shared__ __align__(16) float s_y[TPB][1024];   // y tiles (live across barrier)
    __shared__ unsigned s_t[34 * 35];                // packed (mo<<16 | u16)
    __shared__ uint2    s_coef[12 * 9];              // half2(c0,c1), half2(c2,c3)
    __shared__ float    s_rs[8], s_rq[8];
    __shared__ float2   s_bn[TPB];

    const int tid = threadIdx.x;
    const int bid = blockIdx.x;
    const int tx  = tid & 31;
    const int tyb = tid >> 5;
    const int lane = tx;

    // ---- prefetch tile 0 while we build the coefficient table ----
    float pre[5];
    prefetch_tile(x, bid, tid, pre);

    // ---- coef table: uniform cubic B-spline + Hermite-folded silu base.
    //      Sentinel row m=11: tile stores w=(silu+1)/8, poly(w)=bw*(8w-1).
    if (tid < 108) {
        const int m = tid / 9, k = tid % 9;
        const float bwk = base_weight[k];
        float c0, c1, c2, c3;
        if (m < 11) {
            c0 = c1 = c2 = c3 = 0.f;
            const float F[4][4] = {
                {1.f, -3.f,  3.f, -1.f},
                {4.f,  0.f, -6.f,  3.f},
                {1.f,  3.f,  3.f, -3.f},
                {0.f,  0.f,  0.f,  1.f}
            };
            const float sc = spline_scaler[k] * (1.0f / 6.0f);
            #pragma unroll
            for (int r = 0; r < 4; r++) {
                int j = m - 3 + r;
                if (j >= 0 && j < 8) {
                    float w = spline_weight[k * 8 + j] * sc;
                    c0 += w * F[r][0]; c1 += w * F[r][1];
                    c2 += w * F[r][2]; c3 += w * F[r][3];
                }
            }
            const float x0 = -2.2f + 0.4f * (float)m;
            const float x1 = x0 + 0.4f;
            const float f0 = silu_f(x0), f1 = silu_f(x1);
            const float sg0 = 1.0f / (1.0f + __expf(-x0));
            const float sg1 = 1.0f / (1.0f + __expf(-x1));
            const float d0 = 0.4f * sg0 * (1.0f + x0 * (1.0f - sg0));
            const float d1 = 0.4f * sg1 * (1.0f + x1 * (1.0f - sg1));
            c0 += bwk * f0;
            c1 += bwk * d0;
            c2 += bwk * (3.0f * (f1 - f0) - 2.0f * d0 - d1);
            c3 += bwk * (2.0f * (f0 - f1) + d0 + d1);
        } else {
            c0 = -bwk; c1 = 8.0f * bwk; c2 = 0.f; c3 = 0.f;
        }
        __half2 h01 = __floats2half2_rn(c0, c1);
        __half2 h23 = __floats2half2_rn(c2, c3);
        uint2 w;
        w.x = *reinterpret_cast<unsigned*>(&h01);
        w.y = *reinterpret_cast<unsigned*>(&h23);
        s_coef[m * 9 + k] = w;
    }

    const char* cbase = (const char*)s_coef;

    // ======================= conv over 4 tiles (pipelined) ==================
    #pragma unroll
    for (int it = 0; it < TPB; it++) {
        // transform prefetched regs -> packed s_t
        #pragma unroll
        for (int j = 0; j < 5; j++) {
            const int i = tid + j * 256;
            if (i < 1156) {
                float v  = pre[j];
                float mu = (v + 2.2f) * 2.5f;
                unsigned w;
                if (mu >= 0.0f && mu < 11.0f) {
                    int m = (int)mu;
                    unsigned u16 = (unsigned)((mu - (float)m) * 65536.0f);
                    w = ((unsigned)(m * 72) << 16) | (u16 & 0xFFFFu);
                } else {
                    float s = silu_f(v);
                    unsigned u16 = (unsigned)((s + 1.0f) * (65536.0f / 8.0f));
                    if (u16 > 65535u) u16 = 65535u;
                    w = (792u << 16) | u16;           // row 11
                }
                s_t[(i / 34) * 35 + (i % 34)] = w;
            }
        }
        __syncthreads();

        // prefetch next tile's halo (latency hidden by the compute below)
        if (it < TPB - 1) prefetch_tile(x, bid + (it + 1) * GRIDF, tid, pre);

        // compute this tile (4 strided rows per thread)
        float lsum = 0.f, lsq = 0.f;
        #pragma unroll
        for (int r = 0; r < 4; r++) {
            const int oy = tyb + r * 8;
            float acc = 0.f;
            #pragma unroll
            for (int dy = 0; dy < 3; dy++) {
                #pragma unroll
                for (int dx = 0; dx < 3; dx++) {
                    const int k = dy * 3 + dx;
                    unsigned w = s_t[(oy + dy) * 35 + (tx + dx)];
                    float u = (float)(w & 0xFFFFu) * (1.0f / 65536.0f);
                    uint2 cw = *(const uint2*)(cbase + (w >> 16) + k * 8);
                    float2 c01 = __half22float2(*reinterpret_cast<__half2*>(&cw.x));
                    float2 c23 = __half22float2(*reinterpret_cast<__half2*>(&cw.y));
                    acc += fmaf(u, fmaf(u, fmaf(u, c23.y, c23.x), c01.y), c01.x);
                }
            }
            s_y[it][oy * 32 + tx] = acc;
            lsum += acc;
            lsq  = fmaf(acc, acc, lsq);
        }

        // per-tile block reduction -> race-free partial slot
        #pragma unroll
        for (int o = 16; o > 0; o >>= 1) {
            lsum += __shfl_down_sync(0xffffffffu, lsum, o);
            lsq  += __shfl_down_sync(0xffffffffu, lsq,  o);
        }
        if (tx == 0) { s_rs[tyb] = lsum; s_rq[tyb] = lsq; }
        __syncthreads();
        if (tid == 0) {
            float s = 0.f, q = 0.f;
            #pragma unroll
            for (int i = 0; i < 8; i++) { s += s_rs[i]; q += s_rq[i]; }
            const int t     = bid + it * GRIDF;
            const int plane = t / 9;
            const int c     = plane & (Cn - 1);
            const int b     = plane >> 6;
            g_psum[c * NPART + b * 9 + t % 9] = s;
            g_psq [c * NPART + b * 9 + t % 9] = q;
        }
    }

    // ======================= grid barrier (all 576 co-resident) ============
    __syncthreads();
    if (tid == 0) {
        __threadfence();
        unsigned snap = *(volatile unsigned*)&g_sense;
        unsigned old  = atomicAdd(&g_count, 1u);
        if (old == GRIDF - 1) {
            *(volatile unsigned*)&g_count = 0u;       // reset for next replay
            __threadfence();
            atomicExch(&g_sense, snap ^ 1u);          // release
        } else {
            while (*(volatile unsigned*)&g_sense == snap) __nanosleep(32);
        }
        __threadfence();
    }
    __syncthreads();

    // ======================= stats: warps 0-3, one tile each ===============
    if (tyb < TPB) {
        const int t = bid + tyb * GRIDF;
        const int c = (t / 9) & (Cn - 1);
        float s = __ldcg(&g_psum[c * NPART + lane]);
        float q = __ldcg(&g_psq [c * NPART + lane]);
        if (lane < NPART - 32) {
            s += __ldcg(&g_psum[c * NPART + lane + 32]);
            q += __ldcg(&g_psq [c * NPART + lane + 32]);
        }
        #pragma unroll
        for (int o = 16; o > 0; o >>= 1) {
            s += __shfl_xor_sync(0xffffffffu, s, o);
            q += __shfl_xor_sync(0xffffffffu, q, o);
        }
        if (lane == 0) {
            const float invN = 1.0f / (float)CNT_PER_CH;
            float mean = s * invN;
            float var  = q * invN - mean * mean;
            float scl  = rsqrtf(var + BN_EPS) * gamma[c];
            s_bn[tyb] = make_float2(scl, fmaf(-mean, scl, beta[c]));
        }
    }
    __syncthreads();

    // ======================= apply BN + ReLU from smem ======================
    const int row  = tid >> 3;
    const int col4 = (tid & 7) * 4;
    #pragma unroll
    for (int it = 0; it < TPB; it++) {
        const int t     = bid + it * GRIDF;
        const int plane = t / 9;
        const int tq    = t % 9;
        const int ty0   = (tq / 3) * 32;
        const int tx0   = (tq % 3) * 32;
        const float2 bn = s_bn[it];

        float4 v = *reinterpret_cast<const float4*>(&s_y[it][row * 32 + col4]);
        float4 o;
        o.x = fmaxf(fmaf(v.x, bn.x, bn.y), 0.0f);
        o.y = fmaxf(fmaf(v.y, bn.x, bn.y), 0.0f);
        o.z = fmaxf(fmaf(v.z, bn.x, bn.y), 0.0f);
        o.w = fmaxf(fmaf(v.w, bn.x, bn.y), 0.0f);
        *reinterpret_cast<float4*>(&out[plane * PLANE + (ty0 + row) * Wn + tx0 + col4]) = o;
    }
}

// ---------------------------------------------------------------------------
extern "C" void kernel_launch(void* const* d_in, const int* in_sizes, int n_in,
                              void* d_out, int out_size)
{
    const float* x             = (const float*)d_in[0];
    const float* base_weight   = (const float*)d_in[1];
    const float* spline_weight = (const float*)d_in[2];
    const float* spline_scaler = (const float*)d_in[3];
    const float* bn_gamma      = (const float*)d_in[4];
    const float* bn_beta       = (const float*)d_in[5];
    float* out                 = (float*)d_out;

    kan_fused_kernel<<<GRIDF, 256>>>(x, base_weight, spline_weight, spline_scaler,
                                     bn_gamma, bn_beta, out);
}